// round 6
// baseline (speedup 1.0000x reference)
#include <cuda_runtime.h>
#include <cuda_bf16.h>
#include <math.h>
#include <stdint.h>

#define NN 8192
#define HH 512
#define TAU 0.8f
#define LAM 0.5f
#define EPSV 1e-8f

#define SROWB 80                 // 64B data + 16B pad per row (bf16: 32 el, int8: 64 el)
#define ABYTES (128 * SROWB)     // 10240
#define STAGEB (2 * ABYTES)      // 20480
#define SMEM_MAIN 40960

__device__ __nv_bfloat16 g_a[2 * NN * HH];     // stacked bf16 inputs
__device__ __nv_bfloat16 g_h[2 * NN * HH];     // stacked hidden
__device__ __nv_bfloat16 g_p[2 * NN * HH];     // stacked projections (mp | sc)
__device__ __nv_bfloat16 g_w1[HH * HH];
__device__ __nv_bfloat16 g_w2[HH * HH];
__device__ int8_t g_q[2 * NN * HH];            // stacked int8 quantized projections
__device__ float g_coef[2 * NN];               // s_i / ||z_i||
__device__ uint32_t g_posb[(size_t)NN * (NN / 32)];
__device__ float g_rowsum[NN], g_colsum[NN], g_pmp[NN], g_psc[NN];

__device__ __forceinline__ uint32_t smem_u32(const void* p) {
    uint32_t a;
    asm("{ .reg .u64 t; cvta.to.shared.u64 t, %1; cvt.u32.u64 %0, t; }" : "=r"(a) : "l"(p));
    return a;
}
__device__ __forceinline__ void cp16(uint32_t s, const void* g) {
    asm volatile("cp.async.cg.shared.global [%0], [%1], 16;" :: "r"(s), "l"(g));
}
#define CP_COMMIT() asm volatile("cp.async.commit_group;" ::: "memory")
#define CP_WAIT1() asm volatile("cp.async.wait_group 1;" ::: "memory")
#define CP_WAIT0() asm volatile("cp.async.wait_group 0;" ::: "memory")

#define LDSM4(R, ADDR) \
    asm volatile("ldmatrix.sync.aligned.m8n8.x4.shared.b16 {%0,%1,%2,%3}, [%4];" \
        : "=r"((R)[0]), "=r"((R)[1]), "=r"((R)[2]), "=r"((R)[3]) : "r"(ADDR))

#define MMABF(C, A, B0, B1) \
    asm volatile("mma.sync.aligned.m16n8k16.row.col.f32.bf16.bf16.f32 " \
        "{%0,%1,%2,%3},{%4,%5,%6,%7},{%8,%9},{%0,%1,%2,%3};" \
        : "+f"((C)[0]), "+f"((C)[1]), "+f"((C)[2]), "+f"((C)[3]) \
        : "r"((A)[0]), "r"((A)[1]), "r"((A)[2]), "r"((A)[3]), "r"(B0), "r"(B1))

#define MMAI8(C, A, B0, B1) \
    asm volatile("mma.sync.aligned.m16n8k32.row.col.s32.s8.s8.s32 " \
        "{%0,%1,%2,%3},{%4,%5,%6,%7},{%8,%9},{%0,%1,%2,%3};" \
        : "+r"((C)[0]), "+r"((C)[1]), "+r"((C)[2]), "+r"((C)[3]) \
        : "r"((A)[0]), "r"((A)[1]), "r"((A)[2]), "r"((A)[3]), "r"(B0), "r"(B1))

__device__ __forceinline__ uint32_t pk2(float a, float b) {
    __nv_bfloat162 t = __floats2bfloat162_rn(a, b);
    return *reinterpret_cast<uint32_t*>(&t);
}

// ---- bf16 mainloop for MLP: 128x128 tile, K=512, kc=32 bf16 ----
__device__ __forceinline__ void gemm_bf16(
    uint32_t dsm32, const __nv_bfloat16* __restrict__ A,
    const __nv_bfloat16* __restrict__ B, float cacc[2][8][4]) {
    const int tid = threadIdx.x;
    const int wid = tid >> 5, lane = tid & 31;
    const int wm = wid >> 1, wn = wid & 1;
    const __nv_bfloat16* srcs[2] = {A, B};

    {
#pragma unroll
        for (int a = 0; a < 2; ++a) {
            uint32_t sb = dsm32 + a * ABYTES;
#pragma unroll
            for (int it = 0; it < 2; ++it) {
                int id = it * 256 + tid;
                int row = id >> 2, cc = id & 3;
                cp16(sb + row * SROWB + cc * 16, srcs[a] + (size_t)row * HH + cc * 8);
            }
        }
        CP_COMMIT();
    }
    const int lrow = lane & 15, lhalf = lane >> 4;

    for (int c = 0; c < 16; ++c) {
        if (c + 1 < 16) {
            const int k0 = (c + 1) * 32;
            const uint32_t st = ((c + 1) & 1) * STAGEB;
#pragma unroll
            for (int a = 0; a < 2; ++a) {
                uint32_t sb = dsm32 + st + a * ABYTES;
#pragma unroll
                for (int it = 0; it < 2; ++it) {
                    int id = it * 256 + tid;
                    int row = id >> 2, cc = id & 3;
                    cp16(sb + row * SROWB + cc * 16, srcs[a] + (size_t)row * HH + k0 + cc * 8);
                }
            }
            CP_COMMIT();
            CP_WAIT1();
        } else {
            CP_WAIT0();
        }
        __syncthreads();
        const uint32_t st = (c & 1) * STAGEB;
        const uint32_t ab = dsm32 + st, bb = dsm32 + st + ABYTES;
#pragma unroll
        for (int kk = 0; kk < 2; ++kk) {
            uint32_t ah[2][4];
#pragma unroll
            for (int mf = 0; mf < 2; ++mf) {
                uint32_t off = (uint32_t)((wm * 32 + mf * 16 + lrow) * SROWB + kk * 32 + lhalf * 16);
                LDSM4(ah[mf], ab + off);
            }
            uint32_t bh[4][4];
#pragma unroll
            for (int nb = 0; nb < 4; ++nb) {
                uint32_t off = (uint32_t)((wn * 64 + nb * 16 + lrow) * SROWB + kk * 32 + lhalf * 16);
                LDSM4(bh[nb], bb + off);
            }
#pragma unroll
            for (int mf = 0; mf < 2; ++mf)
#pragma unroll
                for (int nb = 0; nb < 4; ++nb) {
                    MMABF(cacc[mf][nb * 2 + 0], ah[mf], bh[nb][0], bh[nb][2]);
                    MMABF(cacc[mf][nb * 2 + 1], ah[mf], bh[nb][1], bh[nb][3]);
                }
        }
        __syncthreads();
    }
}

// ---- MLP: C = act(A @ W^T + b) ----
template <bool ELU_>
__global__ void __launch_bounds__(256, 2) mlp_kernel(
    const __nv_bfloat16* __restrict__ A, const float* __restrict__ bias,
    __nv_bfloat16* __restrict__ C, const __nv_bfloat16* __restrict__ W) {
    extern __shared__ __align__(16) char dsm[];
    __shared__ float sbias[128];
    const uint32_t dsm32 = smem_u32(dsm);
    const int tid = threadIdx.x;
    const int wid = tid >> 5, lane = tid & 31;
    const int wm = wid >> 1, wn = wid & 1;
    const int ib = blockIdx.y * 128, jb = blockIdx.x * 128;

    if (tid < 128) sbias[tid] = bias[jb + tid];

    float cacc[2][8][4] = {};
    gemm_bf16(dsm32, A + (size_t)ib * HH, W + (size_t)jb * HH, cacc);
    __syncthreads();

#pragma unroll
    for (int mf = 0; mf < 2; ++mf)
#pragma unroll
        for (int nf = 0; nf < 8; ++nf)
#pragma unroll
            for (int h = 0; h < 2; ++h) {
                int i_l = wm * 32 + mf * 16 + (lane >> 2) + h * 8;
                int j_l = wn * 64 + nf * 8 + (lane & 3) * 2;
                float x0 = cacc[mf][nf][h * 2 + 0] + sbias[j_l];
                float x1 = cacc[mf][nf][h * 2 + 1] + sbias[j_l + 1];
                if (ELU_) {
                    x0 = (x0 > 0.f) ? x0 : expm1f(x0);
                    x1 = (x1 > 0.f) ? x1 : expm1f(x1);
                }
                size_t off = (size_t)(ib + i_l) * HH + jb + j_l;
                *(uint32_t*)(C + off) = pk2(x0, x1);
            }
}

// ---- quantize projected rows to int8 with per-row scale; coef = s/||z|| ----
__global__ void quant_kernel(const __nv_bfloat16* __restrict__ z,
                             int8_t* __restrict__ q, float* __restrict__ coef) {
    const int row = blockIdx.x, t = threadIdx.x;  // 128 threads
    const size_t base = (size_t)row * HH + t * 4;
    float v[4];
#pragma unroll
    for (int k = 0; k < 4; ++k) v[k] = __bfloat162float(z[base + k]);
    float ss = 0.f, mx = 0.f;
#pragma unroll
    for (int k = 0; k < 4; ++k) { ss += v[k] * v[k]; mx = fmaxf(mx, fabsf(v[k])); }
#pragma unroll
    for (int o = 16; o > 0; o >>= 1) {
        ss += __shfl_xor_sync(0xffffffffu, ss, o);
        mx = fmaxf(mx, __shfl_xor_sync(0xffffffffu, mx, o));
    }
    __shared__ float srs[4], srm[4], sS;
    if ((t & 31) == 0) { srs[t >> 5] = ss; srm[t >> 5] = mx; }
    __syncthreads();
    if (t == 0) {
        float tss = srs[0] + srs[1] + srs[2] + srs[3];
        float tmx = fmaxf(fmaxf(srm[0], srm[1]), fmaxf(srm[2], srm[3]));
        float s = tmx * (1.0f / 127.0f) + 1e-30f;
        coef[row] = s * rsqrtf(tss + 1e-30f);
        sS = 1.0f / s;
    }
    __syncthreads();
    const float is = sS;
    char4 qa;
    qa.x = (char)max(-127, min(127, __float2int_rn(v[0] * is)));
    qa.y = (char)max(-127, min(127, __float2int_rn(v[1] * is)));
    qa.z = (char)max(-127, min(127, __float2int_rn(v[2] * is)));
    qa.w = (char)max(-127, min(127, __float2int_rn(v[3] * is)));
    *(char4*)(q + base) = qa;
}

// ---- fused pairwise kernel: int8 MMA + register epilogue ----
__global__ void __launch_bounds__(256, 2) pair_kernel() {
    extern __shared__ __align__(16) char dsm[];
    __shared__ float sjv[128];
    const uint32_t dsm32 = smem_u32(dsm);
    const int tid = threadIdx.x;
    const int wid = tid >> 5, lane = tid & 31;
    const int wm = wid >> 1, wn = wid & 1;
    const int ib = blockIdx.y * 128, jb = blockIdx.x * 128;

    if (tid < 128) sjv[tid] = g_coef[NN + jb + tid];

    const int8_t* qA = g_q + (size_t)ib * HH;
    const int8_t* qB = g_q + (size_t)NN * HH + (size_t)jb * HH;
    const int8_t* srcs[2] = {qA, qB};

    int cacc[2][8][4] = {};

    // prologue chunk 0 (kc = 64 int8 = 64B/row)
    {
#pragma unroll
        for (int a = 0; a < 2; ++a) {
            uint32_t sb = dsm32 + a * ABYTES;
#pragma unroll
            for (int it = 0; it < 2; ++it) {
                int id = it * 256 + tid;
                int row = id >> 2, cc = id & 3;
                cp16(sb + row * SROWB + cc * 16, srcs[a] + (size_t)row * HH + cc * 16);
            }
        }
        CP_COMMIT();
    }
    const int lrow = lane & 15, lhalf = lane >> 4;

    for (int c = 0; c < 8; ++c) {
        if (c + 1 < 8) {
            const int k0 = (c + 1) * 64;
            const uint32_t st = ((c + 1) & 1) * STAGEB;
#pragma unroll
            for (int a = 0; a < 2; ++a) {
                uint32_t sb = dsm32 + st + a * ABYTES;
#pragma unroll
                for (int it = 0; it < 2; ++it) {
                    int id = it * 256 + tid;
                    int row = id >> 2, cc = id & 3;
                    cp16(sb + row * SROWB + cc * 16, srcs[a] + (size_t)row * HH + k0 + cc * 16);
                }
            }
            CP_COMMIT();
            CP_WAIT1();
        } else {
            CP_WAIT0();
        }
        __syncthreads();
        const uint32_t st = (c & 1) * STAGEB;
        const uint32_t ab = dsm32 + st, bb = dsm32 + st + ABYTES;
#pragma unroll
        for (int kk = 0; kk < 2; ++kk) {   // two k=32 steps per 64B chunk
            uint32_t ah[2][4];
#pragma unroll
            for (int mf = 0; mf < 2; ++mf) {
                uint32_t off = (uint32_t)((wm * 32 + mf * 16 + lrow) * SROWB + kk * 32 + lhalf * 16);
                LDSM4(ah[mf], ab + off);
            }
            uint32_t bh[4][4];
#pragma unroll
            for (int nb = 0; nb < 4; ++nb) {
                uint32_t off = (uint32_t)((wn * 64 + nb * 16 + lrow) * SROWB + kk * 32 + lhalf * 16);
                LDSM4(bh[nb], bb + off);
            }
#pragma unroll
            for (int mf = 0; mf < 2; ++mf)
#pragma unroll
                for (int nb = 0; nb < 4; ++nb) {
                    MMAI8(cacc[mf][nb * 2 + 0], ah[mf], bh[nb][0], bh[nb][2]);
                    MMAI8(cacc[mf][nb * 2 + 1], ah[mf], bh[nb][1], bh[nb][3]);
                }
        }
        __syncthreads();
    }

    // ---- register epilogue ----
    float coefi[4];
#pragma unroll
    for (int mh = 0; mh < 4; ++mh) {
        int mf = mh >> 1, h = mh & 1;
        coefi[mh] = g_coef[ib + wm * 32 + mf * 16 + (lane >> 2) + h * 8] * (1.0f / TAU);
    }
    // convert s32 -> exp(cos/tau) in place
#pragma unroll
    for (int mf = 0; mf < 2; ++mf)
#pragma unroll
        for (int nf = 0; nf < 8; ++nf)
#pragma unroll
            for (int cr = 0; cr < 4; ++cr) {
                int j_l = wn * 64 + nf * 8 + (lane & 3) * 2 + (cr & 1);
                float e = __expf((float)cacc[mf][nf][cr] * coefi[mf * 2 + (cr >> 1)] * sjv[j_l]);
                cacc[mf][nf][cr] = __float_as_int(e);
            }

    // row reductions: rowsum + pmp (mask pos[i][j])
    uint32_t urow[4][2];
#pragma unroll
    for (int mh = 0; mh < 4; ++mh) {
        int i_g = ib + wm * 32 + (mh >> 1) * 16 + (lane >> 2) + (mh & 1) * 8;
        size_t pb = (size_t)i_g * (NN / 32) + (jb >> 5) + wn * 2;
        urow[mh][0] = g_posb[pb];
        urow[mh][1] = g_posb[pb + 1];
    }
#pragma unroll
    for (int mh = 0; mh < 4; ++mh) {
        int mf = mh >> 1, h = mh & 1;
        float rs = 0.f, pm = 0.f;
#pragma unroll
        for (int nf = 0; nf < 8; ++nf)
#pragma unroll
            for (int cb = 0; cb < 2; ++cb) {
                int jloc = nf * 8 + (lane & 3) * 2 + cb;
                float e = __int_as_float(cacc[mf][nf][(h << 1) | cb]);
                rs += e;
                if ((urow[mh][jloc >> 5] >> (jloc & 31)) & 1u) pm += e;
            }
        rs += __shfl_xor_sync(0xffffffffu, rs, 1);
        rs += __shfl_xor_sync(0xffffffffu, rs, 2);
        pm += __shfl_xor_sync(0xffffffffu, pm, 1);
        pm += __shfl_xor_sync(0xffffffffu, pm, 2);
        if ((lane & 3) == 0) {
            int i_g = ib + wm * 32 + mf * 16 + (lane >> 2) + h * 8;
            atomicAdd(&g_rowsum[i_g], rs);
            atomicAdd(&g_pmp[i_g], pm);
        }
    }

    // col reductions: colsum + psc (mask pos[j][i])
#pragma unroll
    for (int nf = 0; nf < 8; ++nf)
#pragma unroll
        for (int cb = 0; cb < 2; ++cb) {
            int j_g = jb + wn * 64 + nf * 8 + (lane & 3) * 2 + cb;
            uint32_t ucol = g_posb[(size_t)j_g * (NN / 32) + (ib >> 5) + wm];
            float cs = 0.f, ps = 0.f;
#pragma unroll
            for (int mh = 0; mh < 4; ++mh) {
                int mf = mh >> 1, h = mh & 1;
                float e = __int_as_float(cacc[mf][nf][(h << 1) | cb]);
                cs += e;
                int ibit = mf * 16 + h * 8 + (lane >> 2);
                if ((ucol >> ibit) & 1u) ps += e;
            }
            cs += __shfl_xor_sync(0xffffffffu, cs, 4);
            cs += __shfl_xor_sync(0xffffffffu, cs, 8);
            cs += __shfl_xor_sync(0xffffffffu, cs, 16);
            ps += __shfl_xor_sync(0xffffffffu, ps, 4);
            ps += __shfl_xor_sync(0xffffffffu, ps, 8);
            ps += __shfl_xor_sync(0xffffffffu, ps, 16);
            if (lane < 4) {
                atomicAdd(&g_colsum[j_g], cs);
                atomicAdd(&g_psc[j_g], ps);
            }
        }
}

// ---- small kernels ----
__global__ void zero_kernel() {
    int i = blockIdx.x * blockDim.x + threadIdx.x;
    if (i < NN) { g_rowsum[i] = 0.f; g_colsum[i] = 0.f; g_pmp[i] = 0.f; g_psc[i] = 0.f; }
}

__global__ void tobf16_kernel(const float* __restrict__ x,
                              __nv_bfloat16* __restrict__ o, int n8) {
    int t = blockIdx.x * blockDim.x + threadIdx.x;
    if (t >= n8) return;
    size_t b = (size_t)t * 8;
    float4 v0 = *(const float4*)(x + b);
    float4 v1 = *(const float4*)(x + b + 4);
    uint4 vh;
    vh.x = pk2(v0.x, v0.y); vh.y = pk2(v0.z, v0.w);
    vh.z = pk2(v1.x, v1.y); vh.w = pk2(v1.z, v1.w);
    *(uint4*)(o + b) = vh;
}

__global__ void posbits_kernel(const int* __restrict__ pos) {
    int row = blockIdx.x;
    int w0 = threadIdx.x >> 5, lid = threadIdx.x & 31;
    for (int w = w0; w < NN / 32; w += 8) {
        int v = pos[(size_t)row * NN + w * 32 + lid];
        unsigned m = __ballot_sync(0xffffffffu, v != 0);
        if (lid == 0) g_posb[(size_t)row * (NN / 32) + w] = m;
    }
}

__global__ void final_kernel(float* __restrict__ out) {
    int t = threadIdx.x;
    float s = 0.f;
    for (int i = t; i < NN; i += 256) {
        float lmp = logf(g_pmp[i]) - logf(g_rowsum[i] + EPSV);
        float lsc = logf(g_psc[i]) - logf(g_colsum[i] + EPSV);
        s += LAM * lmp + (1.0f - LAM) * lsc;
    }
#pragma unroll
    for (int o = 16; o > 0; o >>= 1) s += __shfl_down_sync(0xffffffffu, s, o);
    __shared__ float sr[8];
    if ((t & 31) == 0) sr[t >> 5] = s;
    __syncthreads();
    if (t == 0) {
        float tot = 0.f;
#pragma unroll
        for (int w = 0; w < 8; w++) tot += sr[w];
        out[0] = -tot / (float)NN;
    }
}

extern "C" void kernel_launch(void* const* d_in, const int* in_sizes, int n_in,
                              void* d_out, int out_size) {
    const float* z_mp = (const float*)d_in[0];
    const float* z_sc = (const float*)d_in[1];
    const int* pos = (const int*)d_in[2];
    const float* W1 = (const float*)d_in[3];
    const float* b1 = (const float*)d_in[4];
    const float* W2 = (const float*)d_in[5];
    const float* b2 = (const float*)d_in[6];

    __nv_bfloat16 *a, *h, *p, *w1, *w2;
    int8_t* q;
    float* coef;
    cudaGetSymbolAddress((void**)&a, g_a);
    cudaGetSymbolAddress((void**)&h, g_h);
    cudaGetSymbolAddress((void**)&p, g_p);
    cudaGetSymbolAddress((void**)&w1, g_w1);
    cudaGetSymbolAddress((void**)&w2, g_w2);
    cudaGetSymbolAddress((void**)&q, g_q);
    cudaGetSymbolAddress((void**)&coef, g_coef);

    static bool attr_done = false;
    if (!attr_done) {
        cudaFuncSetAttribute(mlp_kernel<true>, cudaFuncAttributeMaxDynamicSharedMemorySize, SMEM_MAIN);
        cudaFuncSetAttribute(mlp_kernel<false>, cudaFuncAttributeMaxDynamicSharedMemorySize, SMEM_MAIN);
        cudaFuncSetAttribute(pair_kernel, cudaFuncAttributeMaxDynamicSharedMemorySize, SMEM_MAIN);
        attr_done = true;
    }

    zero_kernel<<<NN / 256, 256>>>();
    posbits_kernel<<<NN, 256>>>(pos);

    tobf16_kernel<<<(NN * HH / 8 + 255) / 256, 256>>>(z_mp, a, NN * HH / 8);
    tobf16_kernel<<<(NN * HH / 8 + 255) / 256, 256>>>(z_sc, a + (size_t)NN * HH, NN * HH / 8);
    tobf16_kernel<<<(HH * HH / 8 + 255) / 256, 256>>>(W1, w1, HH * HH / 8);
    tobf16_kernel<<<(HH * HH / 8 + 255) / 256, 256>>>(W2, w2, HH * HH / 8);

    // stacked MLP: both views through one chain
    dim3 mg(HH / 128, 2 * NN / 128);
    mlp_kernel<true><<<mg, 256, SMEM_MAIN>>>(a, b1, h, w1);
    mlp_kernel<false><<<mg, 256, SMEM_MAIN>>>(h, b2, p, w2);

    // quantize projections (stacked)
    quant_kernel<<<2 * NN, 128>>>(p, q, coef);

    pair_kernel<<<dim3(NN / 128, NN / 128), 256, SMEM_MAIN>>>();

    final_kernel<<<1, 256>>>((float*)d_out);
}

// round 7
// speedup vs baseline: 1.0031x; 1.0031x over previous
#include <cuda_runtime.h>
#include <cuda_bf16.h>
#include <math.h>
#include <stdint.h>

#define NN 8192
#define HH 512
#define TAU 0.8f
#define LAM 0.5f
#define EPSV 1e-8f

#define SROWB 80                 // 64B data + 16B pad per row
#define ABYTES (128 * SROWB)     // 10240
#define STAGEB (2 * ABYTES)      // 20480
#define SMEM_MLP 40960
#define ETS 133
#define SMEM_PAIR 69632          // max(40960 mainloop, 128*133*4=68096 ET)

__device__ __nv_bfloat16 g_a[2 * NN * HH];
__device__ __nv_bfloat16 g_h[2 * NN * HH];
__device__ __nv_bfloat16 g_p[2 * NN * HH];
__device__ __nv_bfloat16 g_w1[HH * HH];
__device__ __nv_bfloat16 g_w2[HH * HH];
__device__ int8_t g_q[2 * NN * HH];
__device__ float g_coef[2 * NN];     // (max/127) / ||z||  per row
__device__ uint32_t g_posb[(size_t)NN * (NN / 32)];
__device__ float g_rowsum[NN], g_colsum[NN], g_pmp[NN], g_psc[NN];

__device__ __forceinline__ uint32_t smem_u32(const void* p) {
    uint32_t a;
    asm("{ .reg .u64 t; cvta.to.shared.u64 t, %1; cvt.u32.u64 %0, t; }" : "=r"(a) : "l"(p));
    return a;
}
__device__ __forceinline__ void cp16(uint32_t s, const void* g) {
    asm volatile("cp.async.cg.shared.global [%0], [%1], 16;" :: "r"(s), "l"(g));
}
#define CP_COMMIT() asm volatile("cp.async.commit_group;" ::: "memory")
#define CP_WAIT1() asm volatile("cp.async.wait_group 1;" ::: "memory")
#define CP_WAIT0() asm volatile("cp.async.wait_group 0;" ::: "memory")

#define LDSM4(R, ADDR) \
    asm volatile("ldmatrix.sync.aligned.m8n8.x4.shared.b16 {%0,%1,%2,%3}, [%4];" \
        : "=r"((R)[0]), "=r"((R)[1]), "=r"((R)[2]), "=r"((R)[3]) : "r"(ADDR))

#define MMABF(C, A, B0, B1) \
    asm volatile("mma.sync.aligned.m16n8k16.row.col.f32.bf16.bf16.f32 " \
        "{%0,%1,%2,%3},{%4,%5,%6,%7},{%8,%9},{%0,%1,%2,%3};" \
        : "+f"((C)[0]), "+f"((C)[1]), "+f"((C)[2]), "+f"((C)[3]) \
        : "r"((A)[0]), "r"((A)[1]), "r"((A)[2]), "r"((A)[3]), "r"(B0), "r"(B1))

#define MMAI8(C, A, B0, B1) \
    asm volatile("mma.sync.aligned.m16n8k32.row.col.s32.s8.s8.s32 " \
        "{%0,%1,%2,%3},{%4,%5,%6,%7},{%8,%9},{%0,%1,%2,%3};" \
        : "+r"((C)[0]), "+r"((C)[1]), "+r"((C)[2]), "+r"((C)[3]) \
        : "r"((A)[0]), "r"((A)[1]), "r"((A)[2]), "r"((A)[3]), "r"(B0), "r"(B1))

__device__ __forceinline__ uint32_t pk2(float a, float b) {
    __nv_bfloat162 t = __floats2bfloat162_rn(a, b);
    return *reinterpret_cast<uint32_t*>(&t);
}

// ---- bf16 mainloop (MLP): 128x128 tile, K=512, kc=32 bf16 ----
__device__ __forceinline__ void gemm_bf16(
    uint32_t dsm32, const __nv_bfloat16* __restrict__ A,
    const __nv_bfloat16* __restrict__ B, float cacc[2][8][4]) {
    const int tid = threadIdx.x;
    const int wid = tid >> 5, lane = tid & 31;
    const int wm = wid >> 1, wn = wid & 1;
    const __nv_bfloat16* srcs[2] = {A, B};

    {
#pragma unroll
        for (int a = 0; a < 2; ++a) {
            uint32_t sb = dsm32 + a * ABYTES;
#pragma unroll
            for (int it = 0; it < 2; ++it) {
                int id = it * 256 + tid;
                int row = id >> 2, cc = id & 3;
                cp16(sb + row * SROWB + cc * 16, srcs[a] + (size_t)row * HH + cc * 8);
            }
        }
        CP_COMMIT();
    }
    const int lrow = lane & 15, lhalf = lane >> 4;

    for (int c = 0; c < 16; ++c) {
        if (c + 1 < 16) {
            const int k0 = (c + 1) * 32;
            const uint32_t st = ((c + 1) & 1) * STAGEB;
#pragma unroll
            for (int a = 0; a < 2; ++a) {
                uint32_t sb = dsm32 + st + a * ABYTES;
#pragma unroll
                for (int it = 0; it < 2; ++it) {
                    int id = it * 256 + tid;
                    int row = id >> 2, cc = id & 3;
                    cp16(sb + row * SROWB + cc * 16, srcs[a] + (size_t)row * HH + k0 + cc * 8);
                }
            }
            CP_COMMIT();
            CP_WAIT1();
        } else {
            CP_WAIT0();
        }
        __syncthreads();
        const uint32_t st = (c & 1) * STAGEB;
        const uint32_t ab = dsm32 + st, bb = dsm32 + st + ABYTES;
#pragma unroll
        for (int kk = 0; kk < 2; ++kk) {
            uint32_t ah[2][4];
#pragma unroll
            for (int mf = 0; mf < 2; ++mf) {
                uint32_t off = (uint32_t)((wm * 32 + mf * 16 + lrow) * SROWB + kk * 32 + lhalf * 16);
                LDSM4(ah[mf], ab + off);
            }
            uint32_t bh[4][4];
#pragma unroll
            for (int nb = 0; nb < 4; ++nb) {
                uint32_t off = (uint32_t)((wn * 64 + nb * 16 + lrow) * SROWB + kk * 32 + lhalf * 16);
                LDSM4(bh[nb], bb + off);
            }
#pragma unroll
            for (int mf = 0; mf < 2; ++mf)
#pragma unroll
                for (int nb = 0; nb < 4; ++nb) {
                    MMABF(cacc[mf][nb * 2 + 0], ah[mf], bh[nb][0], bh[nb][2]);
                    MMABF(cacc[mf][nb * 2 + 1], ah[mf], bh[nb][1], bh[nb][3]);
                }
        }
        __syncthreads();
    }
}

// ---- MLP: C = act(A @ W^T + b) ----
template <bool ELU_>
__global__ void __launch_bounds__(256, 2) mlp_kernel(
    const __nv_bfloat16* __restrict__ A, const float* __restrict__ bias,
    __nv_bfloat16* __restrict__ C, const __nv_bfloat16* __restrict__ W) {
    extern __shared__ __align__(16) char dsm[];
    __shared__ float sbias[128];
    const uint32_t dsm32 = smem_u32(dsm);
    const int tid = threadIdx.x;
    const int wid = tid >> 5, lane = tid & 31;
    const int wm = wid >> 1, wn = wid & 1;
    const int ib = blockIdx.y * 128, jb = blockIdx.x * 128;

    if (tid < 128) sbias[tid] = bias[jb + tid];

    float cacc[2][8][4] = {};
    gemm_bf16(dsm32, A + (size_t)ib * HH, W + (size_t)jb * HH, cacc);
    __syncthreads();

#pragma unroll
    for (int mf = 0; mf < 2; ++mf)
#pragma unroll
        for (int nf = 0; nf < 8; ++nf)
#pragma unroll
            for (int h = 0; h < 2; ++h) {
                int i_l = wm * 32 + mf * 16 + (lane >> 2) + h * 8;
                int j_l = wn * 64 + nf * 8 + (lane & 3) * 2;
                float x0 = cacc[mf][nf][h * 2 + 0] + sbias[j_l];
                float x1 = cacc[mf][nf][h * 2 + 1] + sbias[j_l + 1];
                if (ELU_) {
                    x0 = (x0 > 0.f) ? x0 : expm1f(x0);
                    x1 = (x1 > 0.f) ? x1 : expm1f(x1);
                }
                size_t off = (size_t)(ib + i_l) * HH + jb + j_l;
                *(uint32_t*)(C + off) = pk2(x0, x1);
            }
}

// ---- quantize rows to int8; coef = (max/127)/||z|| ----
__global__ void quant_kernel(const __nv_bfloat16* __restrict__ z,
                             int8_t* __restrict__ q, float* __restrict__ coef) {
    const int row = blockIdx.x, t = threadIdx.x;  // 128 threads
    const size_t base = (size_t)row * HH + t * 4;
    float v[4];
#pragma unroll
    for (int k = 0; k < 4; ++k) v[k] = __bfloat162float(z[base + k]);
    float ss = 0.f, mx = 0.f;
#pragma unroll
    for (int k = 0; k < 4; ++k) { ss += v[k] * v[k]; mx = fmaxf(mx, fabsf(v[k])); }
#pragma unroll
    for (int o = 16; o > 0; o >>= 1) {
        ss += __shfl_xor_sync(0xffffffffu, ss, o);
        mx = fmaxf(mx, __shfl_xor_sync(0xffffffffu, mx, o));
    }
    __shared__ float srs[4], srm[4], sS;
    if ((t & 31) == 0) { srs[t >> 5] = ss; srm[t >> 5] = mx; }
    __syncthreads();
    if (t == 0) {
        float tss = srs[0] + srs[1] + srs[2] + srs[3];
        float tmx = fmaxf(fmaxf(srm[0], srm[1]), fmaxf(srm[2], srm[3]));
        float s = tmx * (1.0f / 127.0f) + 1e-30f;
        coef[row] = s * rsqrtf(tss + 1e-30f);
        sS = 1.0f / s;
    }
    __syncthreads();
    const float is = sS;
    char4 qa;
    qa.x = (char)max(-127, min(127, __float2int_rn(v[0] * is)));
    qa.y = (char)max(-127, min(127, __float2int_rn(v[1] * is)));
    qa.z = (char)max(-127, min(127, __float2int_rn(v[2] * is)));
    qa.w = (char)max(-127, min(127, __float2int_rn(v[3] * is)));
    *(char4*)(q + base) = qa;
}

// ---- fused pairwise kernel: int8 MMA mainloop + smem-tile epilogue ----
__global__ void __launch_bounds__(256, 2) pair_kernel() {
    extern __shared__ __align__(16) char dsm[];
    __shared__ float sjv[128];
    const uint32_t dsm32 = smem_u32(dsm);
    const int tid = threadIdx.x;
    const int wid = tid >> 5, lane = tid & 31;
    const int wm = wid >> 1, wn = wid & 1;
    const int ib = blockIdx.y * 128, jb = blockIdx.x * 128;

    if (tid < 128) sjv[tid] = g_coef[NN + jb + tid];

    const int8_t* qA = g_q + (size_t)ib * HH;
    const int8_t* qB = g_q + (size_t)NN * HH + (size_t)jb * HH;
    const int8_t* srcs[2] = {qA, qB};

    int cacc[2][8][4] = {};

    // prologue chunk 0 (kc = 64 int8 = 64B/row)
    {
#pragma unroll
        for (int a = 0; a < 2; ++a) {
            uint32_t sb = dsm32 + a * ABYTES;
#pragma unroll
            for (int it = 0; it < 2; ++it) {
                int id = it * 256 + tid;
                int row = id >> 2, cc = id & 3;
                cp16(sb + row * SROWB + cc * 16, srcs[a] + (size_t)row * HH + cc * 16);
            }
        }
        CP_COMMIT();
    }
    const int lrow = lane & 15, lhalf = lane >> 4;

    for (int c = 0; c < 8; ++c) {
        if (c + 1 < 8) {
            const int k0 = (c + 1) * 64;
            const uint32_t st = ((c + 1) & 1) * STAGEB;
#pragma unroll
            for (int a = 0; a < 2; ++a) {
                uint32_t sb = dsm32 + st + a * ABYTES;
#pragma unroll
                for (int it = 0; it < 2; ++it) {
                    int id = it * 256 + tid;
                    int row = id >> 2, cc = id & 3;
                    cp16(sb + row * SROWB + cc * 16, srcs[a] + (size_t)row * HH + k0 + cc * 16);
                }
            }
            CP_COMMIT();
            CP_WAIT1();
        } else {
            CP_WAIT0();
        }
        __syncthreads();
        const uint32_t st = (c & 1) * STAGEB;
        const uint32_t ab = dsm32 + st, bb = dsm32 + st + ABYTES;
#pragma unroll
        for (int kk = 0; kk < 2; ++kk) {
            uint32_t ah[2][4];
#pragma unroll
            for (int mf = 0; mf < 2; ++mf) {
                uint32_t off = (uint32_t)((wm * 32 + mf * 16 + lrow) * SROWB + kk * 32 + lhalf * 16);
                LDSM4(ah[mf], ab + off);
            }
            uint32_t bh[4][4];
#pragma unroll
            for (int nb = 0; nb < 4; ++nb) {
                uint32_t off = (uint32_t)((wn * 64 + nb * 16 + lrow) * SROWB + kk * 32 + lhalf * 16);
                LDSM4(bh[nb], bb + off);
            }
#pragma unroll
            for (int mf = 0; mf < 2; ++mf)
#pragma unroll
                for (int nb = 0; nb < 4; ++nb) {
                    MMAI8(cacc[mf][nb * 2 + 0], ah[mf], bh[nb][0], bh[nb][2]);
                    MMAI8(cacc[mf][nb * 2 + 1], ah[mf], bh[nb][1], bh[nb][3]);
                }
        }
        __syncthreads();
    }

    // ---- epilogue: exp -> smem tile (coalesced posb reductions) ----
    float* ET = (float*)dsm;
    float coefi[2][2];
#pragma unroll
    for (int mf = 0; mf < 2; ++mf)
#pragma unroll
        for (int h = 0; h < 2; ++h)
            coefi[mf][h] = g_coef[ib + wm * 32 + mf * 16 + (lane >> 2) + h * 8] * (1.0f / TAU);

#pragma unroll
    for (int mf = 0; mf < 2; ++mf)
#pragma unroll
        for (int nf = 0; nf < 8; ++nf)
#pragma unroll
            for (int cr = 0; cr < 4; ++cr) {
                int i_l = wm * 32 + mf * 16 + (lane >> 2) + (cr >> 1) * 8;
                int j_l = wn * 64 + nf * 8 + (lane & 3) * 2 + (cr & 1);
                float e = __expf((float)cacc[mf][nf][cr] * coefi[mf][cr >> 1] * sjv[j_l]);
                ET[i_l * ETS + j_l] = e;
            }
    __syncthreads();

    if (tid < 128) {
        const int r = tid;
        const float* row = ET + r * ETS;
        float rs = 0.f, pm = 0.f;
        const size_t pb = (size_t)(ib + r) * (NN / 32) + (jb >> 5);
#pragma unroll
        for (int w = 0; w < 4; ++w) {
            uint32_t u = g_posb[pb + w];
#pragma unroll
            for (int b = 0; b < 32; ++b) {
                float e = row[w * 32 + b];
                rs += e;
                if ((u >> b) & 1u) pm += e;
            }
        }
        atomicAdd(&g_rowsum[ib + r], rs);
        atomicAdd(&g_pmp[ib + r], pm);
    } else {
        const int cidx = tid - 128;
        float cs = 0.f, ps = 0.f;
        const size_t pb = (size_t)(jb + cidx) * (NN / 32) + (ib >> 5);
#pragma unroll
        for (int w = 0; w < 4; ++w) {
            uint32_t u = g_posb[pb + w];
#pragma unroll
            for (int b = 0; b < 32; ++b) {
                float e = ET[(w * 32 + b) * ETS + cidx];
                cs += e;
                if ((u >> b) & 1u) ps += e;
            }
        }
        atomicAdd(&g_colsum[jb + cidx], cs);
        atomicAdd(&g_psc[jb + cidx], ps);
    }
}

// ---- small kernels ----
__global__ void zero_kernel() {
    int i = blockIdx.x * blockDim.x + threadIdx.x;
    if (i < NN) { g_rowsum[i] = 0.f; g_colsum[i] = 0.f; g_pmp[i] = 0.f; g_psc[i] = 0.f; }
}

__global__ void tobf16_kernel(const float* __restrict__ x,
                              __nv_bfloat16* __restrict__ o, int n8) {
    int t = blockIdx.x * blockDim.x + threadIdx.x;
    if (t >= n8) return;
    size_t b = (size_t)t * 8;
    float4 v0 = *(const float4*)(x + b);
    float4 v1 = *(const float4*)(x + b + 4);
    uint4 vh;
    vh.x = pk2(v0.x, v0.y); vh.y = pk2(v0.z, v0.w);
    vh.z = pk2(v1.x, v1.y); vh.w = pk2(v1.z, v1.w);
    *(uint4*)(o + b) = vh;
}

__global__ void posbits_kernel(const int* __restrict__ pos) {
    int row = blockIdx.x;
    int w0 = threadIdx.x >> 5, lid = threadIdx.x & 31;
    for (int w = w0; w < NN / 32; w += 8) {
        int v = pos[(size_t)row * NN + w * 32 + lid];
        unsigned m = __ballot_sync(0xffffffffu, v != 0);
        if (lid == 0) g_posb[(size_t)row * (NN / 32) + w] = m;
    }
}

__global__ void final_kernel(float* __restrict__ out) {
    int t = threadIdx.x;
    float s = 0.f;
    for (int i = t; i < NN; i += 256) {
        float lmp = logf(g_pmp[i]) - logf(g_rowsum[i] + EPSV);
        float lsc = logf(g_psc[i]) - logf(g_colsum[i] + EPSV);
        s += LAM * lmp + (1.0f - LAM) * lsc;
    }
#pragma unroll
    for (int o = 16; o > 0; o >>= 1) s += __shfl_down_sync(0xffffffffu, s, o);
    __shared__ float sr[8];
    if ((t & 31) == 0) sr[t >> 5] = s;
    __syncthreads();
    if (t == 0) {
        float tot = 0.f;
#pragma unroll
        for (int w = 0; w < 8; w++) tot += sr[w];
        out[0] = -tot / (float)NN;
    }
}

extern "C" void kernel_launch(void* const* d_in, const int* in_sizes, int n_in,
                              void* d_out, int out_size) {
    const float* z_mp = (const float*)d_in[0];
    const float* z_sc = (const float*)d_in[1];
    const int* pos = (const int*)d_in[2];
    const float* W1 = (const float*)d_in[3];
    const float* b1 = (const float*)d_in[4];
    const float* W2 = (const float*)d_in[5];
    const float* b2 = (const float*)d_in[6];

    __nv_bfloat16 *a, *h, *p, *w1, *w2;
    int8_t* q;
    float* coef;
    cudaGetSymbolAddress((void**)&a, g_a);
    cudaGetSymbolAddress((void**)&h, g_h);
    cudaGetSymbolAddress((void**)&p, g_p);
    cudaGetSymbolAddress((void**)&w1, g_w1);
    cudaGetSymbolAddress((void**)&w2, g_w2);
    cudaGetSymbolAddress((void**)&q, g_q);
    cudaGetSymbolAddress((void**)&coef, g_coef);

    static bool attr_done = false;
    if (!attr_done) {
        cudaFuncSetAttribute(mlp_kernel<true>, cudaFuncAttributeMaxDynamicSharedMemorySize, SMEM_MLP);
        cudaFuncSetAttribute(mlp_kernel<false>, cudaFuncAttributeMaxDynamicSharedMemorySize, SMEM_MLP);
        cudaFuncSetAttribute(pair_kernel, cudaFuncAttributeMaxDynamicSharedMemorySize, SMEM_PAIR);
        attr_done = true;
    }

    zero_kernel<<<NN / 256, 256>>>();
    posbits_kernel<<<NN, 256>>>(pos);

    tobf16_kernel<<<(NN * HH / 8 + 255) / 256, 256>>>(z_mp, a, NN * HH / 8);
    tobf16_kernel<<<(NN * HH / 8 + 255) / 256, 256>>>(z_sc, a + (size_t)NN * HH, NN * HH / 8);
    tobf16_kernel<<<(HH * HH / 8 + 255) / 256, 256>>>(W1, w1, HH * HH / 8);
    tobf16_kernel<<<(HH * HH / 8 + 255) / 256, 256>>>(W2, w2, HH * HH / 8);

    dim3 mg(HH / 128, 2 * NN / 128);
    mlp_kernel<true><<<mg, 256, SMEM_MLP>>>(a, b1, h, w1);
    mlp_kernel<false><<<mg, 256, SMEM_MLP>>>(h, b2, p, w2);

    quant_kernel<<<2 * NN, 128>>>(p, q, coef);

    pair_kernel<<<dim3(NN / 128, NN / 128), 256, SMEM_PAIR>>>();

    final_kernel<<<1, 256>>>((float*)d_out);
}

// round 9
// speedup vs baseline: 1.4212x; 1.4168x over previous
#include <cuda_runtime.h>
#include <cuda_bf16.h>
#include <cuda_fp16.h>
#include <math.h>
#include <stdint.h>

#define NN 8192
#define HH 512
#define TAU 0.8f
#define LAM 0.5f
#define EPSV 1e-8f
#define L2E 1.44269504f

#define SROWB 80                 // 64B data + 16B pad per row (32 bf16)
#define ABYTES (128 * SROWB)     // 10240
#define STAGEB (2 * ABYTES)      // 20480
#define SMEM_MLP 40960
#define ETS 133
#define SMEM_PAIR 69632

__device__ __nv_bfloat16 g_a[2 * NN * HH];
__device__ __nv_bfloat16 g_h[2 * NN * HH];
__device__ __nv_bfloat16 g_p[2 * NN * HH];   // stacked projections (mp | sc)
__device__ __nv_bfloat16 g_w1[HH * HH];
__device__ __nv_bfloat16 g_w2[HH * HH];
__device__ float g_inv[2 * NN];              // 1/||z|| stacked (mp | sc)
__device__ uint32_t g_posb[(size_t)NN * (NN / 32)];
__device__ float g_rowsum[NN], g_colsum[NN], g_pmp[NN], g_psc[NN];

__device__ __forceinline__ uint32_t smem_u32(const void* p) {
    uint32_t a;
    asm("{ .reg .u64 t; cvta.to.shared.u64 t, %1; cvt.u32.u64 %0, t; }" : "=r"(a) : "l"(p));
    return a;
}
__device__ __forceinline__ void cp16(uint32_t s, const void* g) {
    asm volatile("cp.async.cg.shared.global [%0], [%1], 16;" :: "r"(s), "l"(g));
}
#define CP_COMMIT() asm volatile("cp.async.commit_group;" ::: "memory")
#define CP_WAIT1() asm volatile("cp.async.wait_group 1;" ::: "memory")
#define CP_WAIT0() asm volatile("cp.async.wait_group 0;" ::: "memory")

#define LDSM4(R, ADDR) \
    asm volatile("ldmatrix.sync.aligned.m8n8.x4.shared.b16 {%0,%1,%2,%3}, [%4];" \
        : "=r"((R)[0]), "=r"((R)[1]), "=r"((R)[2]), "=r"((R)[3]) : "r"(ADDR))

#define MMABF(C, A, B0, B1) \
    asm volatile("mma.sync.aligned.m16n8k16.row.col.f32.bf16.bf16.f32 " \
        "{%0,%1,%2,%3},{%4,%5,%6,%7},{%8,%9},{%0,%1,%2,%3};" \
        : "+f"((C)[0]), "+f"((C)[1]), "+f"((C)[2]), "+f"((C)[3]) \
        : "r"((A)[0]), "r"((A)[1]), "r"((A)[2]), "r"((A)[3]), "r"(B0), "r"(B1))

__device__ __forceinline__ uint32_t pk2(float a, float b) {
    __nv_bfloat162 t = __floats2bfloat162_rn(a, b);
    return *reinterpret_cast<uint32_t*>(&t);
}

// ---- bf16 mainloop: 128x128 tile, K=512, kc=32 ----
__device__ __forceinline__ void gemm_bf16(
    uint32_t dsm32, const __nv_bfloat16* __restrict__ A,
    const __nv_bfloat16* __restrict__ B, float cacc[2][8][4]) {
    const int tid = threadIdx.x;
    const int wid = tid >> 5, lane = tid & 31;
    const int wm = wid >> 1, wn = wid & 1;
    const __nv_bfloat16* srcs[2] = {A, B};

    {
#pragma unroll
        for (int a = 0; a < 2; ++a) {
            uint32_t sb = dsm32 + a * ABYTES;
#pragma unroll
            for (int it = 0; it < 2; ++it) {
                int id = it * 256 + tid;
                int row = id >> 2, cc = id & 3;
                cp16(sb + row * SROWB + cc * 16, srcs[a] + (size_t)row * HH + cc * 8);
            }
        }
        CP_COMMIT();
    }
    const int lrow = lane & 15, lhalf = lane >> 4;

    for (int c = 0; c < 16; ++c) {
        if (c + 1 < 16) {
            const int k0 = (c + 1) * 32;
            const uint32_t st = ((c + 1) & 1) * STAGEB;
#pragma unroll
            for (int a = 0; a < 2; ++a) {
                uint32_t sb = dsm32 + st + a * ABYTES;
#pragma unroll
                for (int it = 0; it < 2; ++it) {
                    int id = it * 256 + tid;
                    int row = id >> 2, cc = id & 3;
                    cp16(sb + row * SROWB + cc * 16, srcs[a] + (size_t)row * HH + k0 + cc * 8);
                }
            }
            CP_COMMIT();
            CP_WAIT1();
        } else {
            CP_WAIT0();
        }
        __syncthreads();
        const uint32_t st = (c & 1) * STAGEB;
        const uint32_t ab = dsm32 + st, bb = dsm32 + st + ABYTES;
#pragma unroll
        for (int kk = 0; kk < 2; ++kk) {
            uint32_t ah[2][4];
#pragma unroll
            for (int mf = 0; mf < 2; ++mf) {
                uint32_t off = (uint32_t)((wm * 32 + mf * 16 + lrow) * SROWB + kk * 32 + lhalf * 16);
                LDSM4(ah[mf], ab + off);
            }
            uint32_t bh[4][4];
#pragma unroll
            for (int nb = 0; nb < 4; ++nb) {
                uint32_t off = (uint32_t)((wn * 64 + nb * 16 + lrow) * SROWB + kk * 32 + lhalf * 16);
                LDSM4(bh[nb], bb + off);
            }
#pragma unroll
            for (int mf = 0; mf < 2; ++mf)
#pragma unroll
                for (int nb = 0; nb < 4; ++nb) {
                    MMABF(cacc[mf][nb * 2 + 0], ah[mf], bh[nb][0], bh[nb][2]);
                    MMABF(cacc[mf][nb * 2 + 1], ah[mf], bh[nb][1], bh[nb][3]);
                }
        }
        __syncthreads();
    }
}

// ---- MLP: C = act(A @ W^T + b) ----
template <bool ELU_>
__global__ void __launch_bounds__(256, 2) mlp_kernel(
    const __nv_bfloat16* __restrict__ A, const float* __restrict__ bias,
    __nv_bfloat16* __restrict__ C, const __nv_bfloat16* __restrict__ W) {
    extern __shared__ __align__(16) char dsm[];
    __shared__ float sbias[128];
    const uint32_t dsm32 = smem_u32(dsm);
    const int tid = threadIdx.x;
    const int wid = tid >> 5, lane = tid & 31;
    const int wm = wid >> 1, wn = wid & 1;
    const int ib = blockIdx.y * 128, jb = blockIdx.x * 128;

    if (tid < 128) sbias[tid] = bias[jb + tid];

    float cacc[2][8][4] = {};
    gemm_bf16(dsm32, A + (size_t)ib * HH, W + (size_t)jb * HH, cacc);
    __syncthreads();

#pragma unroll
    for (int mf = 0; mf < 2; ++mf)
#pragma unroll
        for (int nf = 0; nf < 8; ++nf)
#pragma unroll
            for (int h = 0; h < 2; ++h) {
                int i_l = wm * 32 + mf * 16 + (lane >> 2) + h * 8;
                int j_l = wn * 64 + nf * 8 + (lane & 3) * 2;
                float x0 = cacc[mf][nf][h * 2 + 0] + sbias[j_l];
                float x1 = cacc[mf][nf][h * 2 + 1] + sbias[j_l + 1];
                if (ELU_) {
                    x0 = (x0 > 0.f) ? x0 : (__expf(x0) - 1.f);
                    x1 = (x1 > 0.f) ? x1 : (__expf(x1) - 1.f);
                }
                size_t off = (size_t)(ib + i_l) * HH + jb + j_l;
                *(uint32_t*)(C + off) = pk2(x0, x1);
            }
}

// ---- fused pairwise kernel: bf16 MMA + f16x2-exp2 smem-tile epilogue ----
__global__ void __launch_bounds__(256, 2) pair_kernel() {
    extern __shared__ __align__(16) char dsm[];
    __shared__ float sjv[128];
    const uint32_t dsm32 = smem_u32(dsm);
    const int tid = threadIdx.x;
    const int wid = tid >> 5, lane = tid & 31;
    const int wm = wid >> 1, wn = wid & 1;
    const int ib = blockIdx.y * 128, jb = blockIdx.x * 128;

    if (tid < 128) sjv[tid] = g_inv[NN + jb + tid];

    // A = mp rows [ib, ib+128);  B = sc rows [jb, jb+128) (second half of g_p)
    const __nv_bfloat16* Aptr = g_p + (size_t)ib * HH;
    const __nv_bfloat16* Bptr = g_p + (size_t)NN * HH + (size_t)jb * HH;

    float cacc[2][8][4] = {};
    gemm_bf16(dsm32, Aptr, Bptr, cacc);
    __syncthreads();

    // exp2 in f16x2 pairs -> smem tile
    float* ET = (float*)dsm;
    float coefi[2][2];   // inv_mp * log2(e) / TAU
#pragma unroll
    for (int mf = 0; mf < 2; ++mf)
#pragma unroll
        for (int h = 0; h < 2; ++h)
            coefi[mf][h] = g_inv[ib + wm * 32 + mf * 16 + (lane >> 2) + h * 8] * (L2E / TAU);

#pragma unroll
    for (int mf = 0; mf < 2; ++mf)
#pragma unroll
        for (int nf = 0; nf < 8; ++nf)
#pragma unroll
            for (int h = 0; h < 2; ++h) {
                int i_l = wm * 32 + mf * 16 + (lane >> 2) + h * 8;
                int j_l = wn * 64 + nf * 8 + (lane & 3) * 2;
                float x0 = cacc[mf][nf][h * 2 + 0] * coefi[mf][h] * sjv[j_l];
                float x1 = cacc[mf][nf][h * 2 + 1] * coefi[mf][h] * sjv[j_l + 1];
                __half2 hx = __floats2half2_rn(x0, x1);
                __half2 he = h2exp2(hx);
                ET[i_l * ETS + j_l] = __low2float(he);
                ET[i_l * ETS + j_l + 1] = __high2float(he);
            }
    __syncthreads();

    if (tid < 128) {
        const int r = tid;
        const float* row = ET + r * ETS;
        float rs = 0.f, pm = 0.f;
        const size_t pb = (size_t)(ib + r) * (NN / 32) + (jb >> 5);
#pragma unroll
        for (int w = 0; w < 4; ++w) {
            uint32_t u = g_posb[pb + w];
#pragma unroll
            for (int b = 0; b < 32; ++b) {
                float e = row[w * 32 + b];
                rs += e;
                if ((u >> b) & 1u) pm += e;
            }
        }
        atomicAdd(&g_rowsum[ib + r], rs);
        atomicAdd(&g_pmp[ib + r], pm);
    } else {
        const int cidx = tid - 128;
        float cs = 0.f, ps = 0.f;
        const size_t pb = (size_t)(jb + cidx) * (NN / 32) + (ib >> 5);
#pragma unroll
        for (int w = 0; w < 4; ++w) {
            uint32_t u = g_posb[pb + w];
#pragma unroll
            for (int b = 0; b < 32; ++b) {
                float e = ET[(w * 32 + b) * ETS + cidx];
                cs += e;
                if ((u >> b) & 1u) ps += e;
            }
        }
        atomicAdd(&g_colsum[jb + cidx], cs);
        atomicAdd(&g_psc[jb + cidx], ps);
    }
}

// ---- small kernels ----
__global__ void zero_kernel() {
    int i = blockIdx.x * blockDim.x + threadIdx.x;
    if (i < NN) { g_rowsum[i] = 0.f; g_colsum[i] = 0.f; g_pmp[i] = 0.f; g_psc[i] = 0.f; }
}

__global__ void tobf16_kernel(const float* __restrict__ x,
                              __nv_bfloat16* __restrict__ o, int n8) {
    int t = blockIdx.x * blockDim.x + threadIdx.x;
    if (t >= n8) return;
    size_t b = (size_t)t * 8;
    float4 v0 = *(const float4*)(x + b);
    float4 v1 = *(const float4*)(x + b + 4);
    uint4 vh;
    vh.x = pk2(v0.x, v0.y); vh.y = pk2(v0.z, v0.w);
    vh.z = pk2(v1.x, v1.y); vh.w = pk2(v1.z, v1.w);
    *(uint4*)(o + b) = vh;
}

__global__ void norm_kernel(const __nv_bfloat16* __restrict__ z, float* __restrict__ inv) {
    int row = blockIdx.x, t = threadIdx.x;  // 128 threads
    size_t base = (size_t)row * HH + t * 4;
    float s = 0.f;
#pragma unroll
    for (int k = 0; k < 4; ++k) {
        float v = __bfloat162float(z[base + k]);
        s += v * v;
    }
#pragma unroll
    for (int o = 16; o > 0; o >>= 1) s += __shfl_xor_sync(0xffffffffu, s, o);
    __shared__ float sr[4];
    if ((t & 31) == 0) sr[t >> 5] = s;
    __syncthreads();
    if (t == 0) inv[row] = rsqrtf(sr[0] + sr[1] + sr[2] + sr[3]);
}

__global__ void posbits_kernel(const int* __restrict__ pos) {
    int row = blockIdx.x;
    int w0 = threadIdx.x >> 5, lid = threadIdx.x & 31;
    for (int w = w0; w < NN / 32; w += 8) {
        int v = pos[(size_t)row * NN + w * 32 + lid];
        unsigned m = __ballot_sync(0xffffffffu, v != 0);
        if (lid == 0) g_posb[(size_t)row * (NN / 32) + w] = m;
    }
}

__global__ void final_kernel(float* __restrict__ out) {
    int t = threadIdx.x;
    float s = 0.f;
    for (int i = t; i < NN; i += 256) {
        float lmp = logf(g_pmp[i]) - logf(g_rowsum[i] + EPSV);
        float lsc = logf(g_psc[i]) - logf(g_colsum[i] + EPSV);
        s += LAM * lmp + (1.0f - LAM) * lsc;
    }
#pragma unroll
    for (int o = 16; o > 0; o >>= 1) s += __shfl_down_sync(0xffffffffu, s, o);
    __shared__ float sr[8];
    if ((t & 31) == 0) sr[t >> 5] = s;
    __syncthreads();
    if (t == 0) {
        float tot = 0.f;
#pragma unroll
        for (int w = 0; w < 8; w++) tot += sr[w];
        out[0] = -tot / (float)NN;
    }
}

extern "C" void kernel_launch(void* const* d_in, const int* in_sizes, int n_in,
                              void* d_out, int out_size) {
    const float* z_mp = (const float*)d_in[0];
    const float* z_sc = (const float*)d_in[1];
    const int* pos = (const int*)d_in[2];
    const float* W1 = (const float*)d_in[3];
    const float* b1 = (const float*)d_in[4];
    const float* W2 = (const float*)d_in[5];
    const float* b2 = (const float*)d_in[6];

    __nv_bfloat16 *a, *h, *p, *w1, *w2;
    float* inv;
    cudaGetSymbolAddress((void**)&a, g_a);
    cudaGetSymbolAddress((void**)&h, g_h);
    cudaGetSymbolAddress((void**)&p, g_p);
    cudaGetSymbolAddress((void**)&w1, g_w1);
    cudaGetSymbolAddress((void**)&w2, g_w2);
    cudaGetSymbolAddress((void**)&inv, g_inv);

    static bool attr_done = false;
    if (!attr_done) {
        cudaFuncSetAttribute(mlp_kernel<true>, cudaFuncAttributeMaxDynamicSharedMemorySize, SMEM_MLP);
        cudaFuncSetAttribute(mlp_kernel<false>, cudaFuncAttributeMaxDynamicSharedMemorySize, SMEM_MLP);
        cudaFuncSetAttribute(pair_kernel, cudaFuncAttributeMaxDynamicSharedMemorySize, SMEM_PAIR);
        attr_done = true;
    }

    zero_kernel<<<NN / 256, 256>>>();
    posbits_kernel<<<NN, 256>>>(pos);

    tobf16_kernel<<<(NN * HH / 8 + 255) / 256, 256>>>(z_mp, a, NN * HH / 8);
    tobf16_kernel<<<(NN * HH / 8 + 255) / 256, 256>>>(z_sc, a + (size_t)NN * HH, NN * HH / 8);
    tobf16_kernel<<<(HH * HH / 8 + 255) / 256, 256>>>(W1, w1, HH * HH / 8);
    tobf16_kernel<<<(HH * HH / 8 + 255) / 256, 256>>>(W2, w2, HH * HH / 8);

    // stacked MLP: both views through one chain (p = [mp | sc])
    dim3 mg(HH / 128, 2 * NN / 128);
    mlp_kernel<true><<<mg, 256, SMEM_MLP>>>(a, b1, h, w1);
    mlp_kernel<false><<<mg, 256, SMEM_MLP>>>(h, b2, p, w2);

    norm_kernel<<<2 * NN, 128>>>(p, inv);

    pair_kernel<<<dim3(NN / 128, NN / 128), 256, SMEM_PAIR>>>();

    final_kernel<<<1, 256>>>((float*)d_out);
}

// round 10
// speedup vs baseline: 1.5069x; 1.0603x over previous
#include <cuda_runtime.h>
#include <cuda_bf16.h>
#include <cuda_fp16.h>
#include <math.h>
#include <stdint.h>

#define NN 8192
#define HH 512
#define TAU 0.8f
#define LAM 0.5f
#define EPSV 1e-8f
#define L2E 1.44269504f

#define SROWB 80                 // 64B data + 16B pad per row (32 x 16-bit)
#define ABYTES (128 * SROWB)     // 10240
#define STAGEB (2 * ABYTES)      // 20480
#define SMEM_MLP 40960
#define ETS 133
#define SMEM_PAIR 69632

__device__ __nv_bfloat16 g_a[2 * NN * HH];
__device__ __nv_bfloat16 g_h[2 * NN * HH];
__device__ __nv_bfloat16 g_p[2 * NN * HH];   // stacked projections (mp | sc)
__device__ __half g_pn[2 * NN * HH];         // normalized rows, f16
__device__ __nv_bfloat16 g_w1[HH * HH];
__device__ __nv_bfloat16 g_w2[HH * HH];
__device__ uint32_t g_posb[(size_t)NN * (NN / 32)];
__device__ float g_rowsum[NN], g_colsum[NN], g_pmp[NN], g_psc[NN];

__device__ __forceinline__ uint32_t smem_u32(const void* p) {
    uint32_t a;
    asm("{ .reg .u64 t; cvta.to.shared.u64 t, %1; cvt.u32.u64 %0, t; }" : "=r"(a) : "l"(p));
    return a;
}
__device__ __forceinline__ void cp16(uint32_t s, const void* g) {
    asm volatile("cp.async.cg.shared.global [%0], [%1], 16;" :: "r"(s), "l"(g));
}
#define CP_COMMIT() asm volatile("cp.async.commit_group;" ::: "memory")
#define CP_WAIT1() asm volatile("cp.async.wait_group 1;" ::: "memory")
#define CP_WAIT0() asm volatile("cp.async.wait_group 0;" ::: "memory")

#define LDSM4(R, ADDR) \
    asm volatile("ldmatrix.sync.aligned.m8n8.x4.shared.b16 {%0,%1,%2,%3}, [%4];" \
        : "=r"((R)[0]), "=r"((R)[1]), "=r"((R)[2]), "=r"((R)[3]) : "r"(ADDR))

#define MMABF(C, A, B0, B1) \
    asm volatile("mma.sync.aligned.m16n8k16.row.col.f32.bf16.bf16.f32 " \
        "{%0,%1,%2,%3},{%4,%5,%6,%7},{%8,%9},{%0,%1,%2,%3};" \
        : "+f"((C)[0]), "+f"((C)[1]), "+f"((C)[2]), "+f"((C)[3]) \
        : "r"((A)[0]), "r"((A)[1]), "r"((A)[2]), "r"((A)[3]), "r"(B0), "r"(B1))

#define MMAF16(C, A, B0, B1) \
    asm volatile("mma.sync.aligned.m16n8k16.row.col.f16.f16.f16.f16 " \
        "{%0,%1},{%2,%3,%4,%5},{%6,%7},{%0,%1};" \
        : "+r"((C)[0]), "+r"((C)[1]) \
        : "r"((A)[0]), "r"((A)[1]), "r"((A)[2]), "r"((A)[3]), "r"(B0), "r"(B1))

__device__ __forceinline__ uint32_t pk2(float a, float b) {
    __nv_bfloat162 t = __floats2bfloat162_rn(a, b);
    return *reinterpret_cast<uint32_t*>(&t);
}

// ---- bf16/f32-accum mainloop (MLP): 128x128 tile, K=512, kc=32 ----
__device__ __forceinline__ void gemm_bf16(
    uint32_t dsm32, const __nv_bfloat16* __restrict__ A,
    const __nv_bfloat16* __restrict__ B, float cacc[2][8][4]) {
    const int tid = threadIdx.x;
    const int wid = tid >> 5, lane = tid & 31;
    const int wm = wid >> 1, wn = wid & 1;
    const __nv_bfloat16* srcs[2] = {A, B};

    {
#pragma unroll
        for (int a = 0; a < 2; ++a) {
            uint32_t sb = dsm32 + a * ABYTES;
#pragma unroll
            for (int it = 0; it < 2; ++it) {
                int id = it * 256 + tid;
                int row = id >> 2, cc = id & 3;
                cp16(sb + row * SROWB + cc * 16, srcs[a] + (size_t)row * HH + cc * 8);
            }
        }
        CP_COMMIT();
    }
    const int lrow = lane & 15, lhalf = lane >> 4;

    for (int c = 0; c < 16; ++c) {
        if (c + 1 < 16) {
            const int k0 = (c + 1) * 32;
            const uint32_t st = ((c + 1) & 1) * STAGEB;
#pragma unroll
            for (int a = 0; a < 2; ++a) {
                uint32_t sb = dsm32 + st + a * ABYTES;
#pragma unroll
                for (int it = 0; it < 2; ++it) {
                    int id = it * 256 + tid;
                    int row = id >> 2, cc = id & 3;
                    cp16(sb + row * SROWB + cc * 16, srcs[a] + (size_t)row * HH + k0 + cc * 8);
                }
            }
            CP_COMMIT();
            CP_WAIT1();
        } else {
            CP_WAIT0();
        }
        __syncthreads();
        const uint32_t st = (c & 1) * STAGEB;
        const uint32_t ab = dsm32 + st, bb = dsm32 + st + ABYTES;
#pragma unroll
        for (int kk = 0; kk < 2; ++kk) {
            uint32_t ah[2][4];
#pragma unroll
            for (int mf = 0; mf < 2; ++mf) {
                uint32_t off = (uint32_t)((wm * 32 + mf * 16 + lrow) * SROWB + kk * 32 + lhalf * 16);
                LDSM4(ah[mf], ab + off);
            }
            uint32_t bh[4][4];
#pragma unroll
            for (int nb = 0; nb < 4; ++nb) {
                uint32_t off = (uint32_t)((wn * 64 + nb * 16 + lrow) * SROWB + kk * 32 + lhalf * 16);
                LDSM4(bh[nb], bb + off);
            }
#pragma unroll
            for (int mf = 0; mf < 2; ++mf)
#pragma unroll
                for (int nb = 0; nb < 4; ++nb) {
                    MMABF(cacc[mf][nb * 2 + 0], ah[mf], bh[nb][0], bh[nb][2]);
                    MMABF(cacc[mf][nb * 2 + 1], ah[mf], bh[nb][1], bh[nb][3]);
                }
        }
        __syncthreads();
    }
}

// ---- MLP: C = act(A @ W^T + b) ----
template <bool ELU_>
__global__ void __launch_bounds__(256, 2) mlp_kernel(
    const __nv_bfloat16* __restrict__ A, const float* __restrict__ bias,
    __nv_bfloat16* __restrict__ C, const __nv_bfloat16* __restrict__ W) {
    extern __shared__ __align__(16) char dsm[];
    __shared__ float sbias[128];
    const uint32_t dsm32 = smem_u32(dsm);
    const int tid = threadIdx.x;
    const int wid = tid >> 5, lane = tid & 31;
    const int wm = wid >> 1, wn = wid & 1;
    const int ib = blockIdx.y * 128, jb = blockIdx.x * 128;

    if (tid < 128) sbias[tid] = bias[jb + tid];

    float cacc[2][8][4] = {};
    gemm_bf16(dsm32, A + (size_t)ib * HH, W + (size_t)jb * HH, cacc);
    __syncthreads();

#pragma unroll
    for (int mf = 0; mf < 2; ++mf)
#pragma unroll
        for (int nf = 0; nf < 8; ++nf)
#pragma unroll
            for (int h = 0; h < 2; ++h) {
                int i_l = wm * 32 + mf * 16 + (lane >> 2) + h * 8;
                int j_l = wn * 64 + nf * 8 + (lane & 3) * 2;
                float x0 = cacc[mf][nf][h * 2 + 0] + sbias[j_l];
                float x1 = cacc[mf][nf][h * 2 + 1] + sbias[j_l + 1];
                if (ELU_) {
                    x0 = (x0 > 0.f) ? x0 : (__expf(x0) - 1.f);
                    x1 = (x1 > 0.f) ? x1 : (__expf(x1) - 1.f);
                }
                size_t off = (size_t)(ib + i_l) * HH + jb + j_l;
                *(uint32_t*)(C + off) = pk2(x0, x1);
            }
}

// ---- fused pairwise kernel: normalized f16, f16-accum MMA ----
__global__ void __launch_bounds__(256, 2) pair_kernel() {
    extern __shared__ __align__(16) char dsm[];
    const uint32_t dsm32 = smem_u32(dsm);
    const int tid = threadIdx.x;
    const int wid = tid >> 5, lane = tid & 31;
    const int wm = wid >> 1, wn = wid & 1;
    const int ib = blockIdx.y * 128, jb = blockIdx.x * 128;

    const __half* Aptr = g_pn + (size_t)ib * HH;
    const __half* Bptr = g_pn + (size_t)NN * HH + (size_t)jb * HH;
    const __half* srcs[2] = {Aptr, Bptr};

    uint32_t cacc[2][8][2] = {};   // packed half2 accumulators

    {
#pragma unroll
        for (int a = 0; a < 2; ++a) {
            uint32_t sb = dsm32 + a * ABYTES;
#pragma unroll
            for (int it = 0; it < 2; ++it) {
                int id = it * 256 + tid;
                int row = id >> 2, cc = id & 3;
                cp16(sb + row * SROWB + cc * 16, srcs[a] + (size_t)row * HH + cc * 8);
            }
        }
        CP_COMMIT();
    }
    const int lrow = lane & 15, lhalf = lane >> 4;

    for (int c = 0; c < 16; ++c) {
        if (c + 1 < 16) {
            const int k0 = (c + 1) * 32;
            const uint32_t st = ((c + 1) & 1) * STAGEB;
#pragma unroll
            for (int a = 0; a < 2; ++a) {
                uint32_t sb = dsm32 + st + a * ABYTES;
#pragma unroll
                for (int it = 0; it < 2; ++it) {
                    int id = it * 256 + tid;
                    int row = id >> 2, cc = id & 3;
                    cp16(sb + row * SROWB + cc * 16, srcs[a] + (size_t)row * HH + k0 + cc * 8);
                }
            }
            CP_COMMIT();
            CP_WAIT1();
        } else {
            CP_WAIT0();
        }
        __syncthreads();
        const uint32_t st = (c & 1) * STAGEB;
        const uint32_t ab = dsm32 + st, bb = dsm32 + st + ABYTES;
#pragma unroll
        for (int kk = 0; kk < 2; ++kk) {
            uint32_t ah[2][4];
#pragma unroll
            for (int mf = 0; mf < 2; ++mf) {
                uint32_t off = (uint32_t)((wm * 32 + mf * 16 + lrow) * SROWB + kk * 32 + lhalf * 16);
                LDSM4(ah[mf], ab + off);
            }
            uint32_t bh[4][4];
#pragma unroll
            for (int nb = 0; nb < 4; ++nb) {
                uint32_t off = (uint32_t)((wn * 64 + nb * 16 + lrow) * SROWB + kk * 32 + lhalf * 16);
                LDSM4(bh[nb], bb + off);
            }
#pragma unroll
            for (int mf = 0; mf < 2; ++mf)
#pragma unroll
                for (int nb = 0; nb < 4; ++nb) {
                    MMAF16(cacc[mf][nb * 2 + 0], ah[mf], bh[nb][0], bh[nb][2]);
                    MMAF16(cacc[mf][nb * 2 + 1], ah[mf], bh[nb][1], bh[nb][3]);
                }
        }
        __syncthreads();
    }

    // ---- epilogue: d is cos in f16; e = exp2(d * L2E/TAU) -> smem tile ----
    float* ET = (float*)dsm;
    const __half2 k2 = __floats2half2_rn(L2E / TAU, L2E / TAU);
#pragma unroll
    for (int mf = 0; mf < 2; ++mf)
#pragma unroll
        for (int nf = 0; nf < 8; ++nf)
#pragma unroll
            for (int r = 0; r < 2; ++r) {
                __half2 d = *reinterpret_cast<__half2*>(&cacc[mf][nf][r]);
                __half2 e = h2exp2(__hmul2(d, k2));
                int i_l = wm * 32 + mf * 16 + (lane >> 2) + r * 8;
                int j_l = wn * 64 + nf * 8 + (lane & 3) * 2;
                ET[i_l * ETS + j_l] = __low2float(e);
                ET[i_l * ETS + j_l + 1] = __high2float(e);
            }
    __syncthreads();

    if (tid < 128) {
        const int r = tid;
        const float* row = ET + r * ETS;
        float rs = 0.f, pm = 0.f;
        const size_t pb = (size_t)(ib + r) * (NN / 32) + (jb >> 5);
#pragma unroll
        for (int w = 0; w < 4; ++w) {
            uint32_t u = g_posb[pb + w];
#pragma unroll
            for (int b = 0; b < 32; ++b) {
                float e = row[w * 32 + b];
                rs += e;
                if ((u >> b) & 1u) pm += e;
            }
        }
        atomicAdd(&g_rowsum[ib + r], rs);
        atomicAdd(&g_pmp[ib + r], pm);
    } else {
        const int cidx = tid - 128;
        float cs = 0.f, ps = 0.f;
        const size_t pb = (size_t)(jb + cidx) * (NN / 32) + (ib >> 5);
#pragma unroll
        for (int w = 0; w < 4; ++w) {
            uint32_t u = g_posb[pb + w];
#pragma unroll
            for (int b = 0; b < 32; ++b) {
                float e = ET[(w * 32 + b) * ETS + cidx];
                cs += e;
                if ((u >> b) & 1u) ps += e;
            }
        }
        atomicAdd(&g_colsum[jb + cidx], cs);
        atomicAdd(&g_psc[jb + cidx], ps);
    }
}

// ---- small kernels ----
__global__ void zero_kernel() {
    int i = blockIdx.x * blockDim.x + threadIdx.x;
    if (i < NN) { g_rowsum[i] = 0.f; g_colsum[i] = 0.f; g_pmp[i] = 0.f; g_psc[i] = 0.f; }
}

__global__ void tobf16_kernel(const float* __restrict__ x,
                              __nv_bfloat16* __restrict__ o, int n8) {
    int t = blockIdx.x * blockDim.x + threadIdx.x;
    if (t >= n8) return;
    size_t b = (size_t)t * 8;
    float4 v0 = *(const float4*)(x + b);
    float4 v1 = *(const float4*)(x + b + 4);
    uint4 vh;
    vh.x = pk2(v0.x, v0.y); vh.y = pk2(v0.z, v0.w);
    vh.z = pk2(v1.x, v1.y); vh.w = pk2(v1.z, v1.w);
    *(uint4*)(o + b) = vh;
}

// normalize projected rows -> f16
__global__ void normf16_kernel(const __nv_bfloat16* __restrict__ z, __half* __restrict__ o) {
    const int row = blockIdx.x, t = threadIdx.x;   // 128 threads
    const size_t base = (size_t)row * HH + t * 4;
    float v[4];
#pragma unroll
    for (int k = 0; k < 4; ++k) v[k] = __bfloat162float(z[base + k]);
    float ss = v[0] * v[0] + v[1] * v[1] + v[2] * v[2] + v[3] * v[3];
#pragma unroll
    for (int off = 16; off > 0; off >>= 1) ss += __shfl_xor_sync(0xffffffffu, ss, off);
    __shared__ float sr[4];
    if ((t & 31) == 0) sr[t >> 5] = ss;
    __syncthreads();
    const float is = rsqrtf(sr[0] + sr[1] + sr[2] + sr[3] + 1e-30f);
    __half2 h0 = __floats2half2_rn(v[0] * is, v[1] * is);
    __half2 h1 = __floats2half2_rn(v[2] * is, v[3] * is);
    *reinterpret_cast<__half2*>(o + base) = h0;
    *reinterpret_cast<__half2*>(o + base + 2) = h1;
}

// one thread per output word; 8 x int4 = one 128B line per thread
__global__ void posbits_kernel(const int* __restrict__ pos) {
    size_t w = (size_t)blockIdx.x * blockDim.x + threadIdx.x;
    if (w >= (size_t)NN * (NN / 32)) return;
    const int4* p = (const int4*)(pos + w * 32);
    uint32_t m = 0;
#pragma unroll
    for (int k = 0; k < 8; ++k) {
        int4 v = p[k];
        m |= (v.x != 0 ? 1u : 0u) << (4 * k);
        m |= (v.y != 0 ? 1u : 0u) << (4 * k + 1);
        m |= (v.z != 0 ? 1u : 0u) << (4 * k + 2);
        m |= (v.w != 0 ? 1u : 0u) << (4 * k + 3);
    }
    g_posb[w] = m;
}

__global__ void final_kernel(float* __restrict__ out) {
    int t = threadIdx.x;
    float s = 0.f;
    for (int i = t; i < NN; i += 256) {
        float lmp = logf(g_pmp[i]) - logf(g_rowsum[i] + EPSV);
        float lsc = logf(g_psc[i]) - logf(g_colsum[i] + EPSV);
        s += LAM * lmp + (1.0f - LAM) * lsc;
    }
#pragma unroll
    for (int o = 16; o > 0; o >>= 1) s += __shfl_down_sync(0xffffffffu, s, o);
    __shared__ float sr[8];
    if ((t & 31) == 0) sr[t >> 5] = s;
    __syncthreads();
    if (t == 0) {
        float tot = 0.f;
#pragma unroll
        for (int w = 0; w < 8; w++) tot += sr[w];
        out[0] = -tot / (float)NN;
    }
}

extern "C" void kernel_launch(void* const* d_in, const int* in_sizes, int n_in,
                              void* d_out, int out_size) {
    const float* z_mp = (const float*)d_in[0];
    const float* z_sc = (const float*)d_in[1];
    const int* pos = (const int*)d_in[2];
    const float* W1 = (const float*)d_in[3];
    const float* b1 = (const float*)d_in[4];
    const float* W2 = (const float*)d_in[5];
    const float* b2 = (const float*)d_in[6];

    __nv_bfloat16 *a, *h, *p, *w1, *w2;
    __half* pn;
    cudaGetSymbolAddress((void**)&a, g_a);
    cudaGetSymbolAddress((void**)&h, g_h);
    cudaGetSymbolAddress((void**)&p, g_p);
    cudaGetSymbolAddress((void**)&pn, g_pn);
    cudaGetSymbolAddress((void**)&w1, g_w1);
    cudaGetSymbolAddress((void**)&w2, g_w2);

    static bool attr_done = false;
    if (!attr_done) {
        cudaFuncSetAttribute(mlp_kernel<true>, cudaFuncAttributeMaxDynamicSharedMemorySize, SMEM_MLP);
        cudaFuncSetAttribute(mlp_kernel<false>, cudaFuncAttributeMaxDynamicSharedMemorySize, SMEM_MLP);
        cudaFuncSetAttribute(pair_kernel, cudaFuncAttributeMaxDynamicSharedMemorySize, SMEM_PAIR);
        attr_done = true;
    }

    zero_kernel<<<NN / 256, 256>>>();
    posbits_kernel<<<(NN * (NN / 32) + 255) / 256, 256>>>(pos);

    tobf16_kernel<<<(NN * HH / 8 + 255) / 256, 256>>>(z_mp, a, NN * HH / 8);
    tobf16_kernel<<<(NN * HH / 8 + 255) / 256, 256>>>(z_sc, a + (size_t)NN * HH, NN * HH / 8);
    tobf16_kernel<<<(HH * HH / 8 + 255) / 256, 256>>>(W1, w1, HH * HH / 8);
    tobf16_kernel<<<(HH * HH / 8 + 255) / 256, 256>>>(W2, w2, HH * HH / 8);

    // stacked MLP: both views through one chain (p = [mp | sc])
    dim3 mg(HH / 128, 2 * NN / 128);
    mlp_kernel<true><<<mg, 256, SMEM_MLP>>>(a, b1, h, w1);
    mlp_kernel<false><<<mg, 256, SMEM_MLP>>>(h, b2, p, w2);

    normf16_kernel<<<2 * NN, 128>>>(p, pn);

    pair_kernel<<<dim3(NN / 128, NN / 128), 256, SMEM_PAIR>>>();

    final_kernel<<<1, 256>>>((float*)d_out);
}